// round 15
// baseline (speedup 1.0000x reference)
#include <cuda_runtime.h>
#include <cuda_bf16.h>
#include <math.h>

// Problem constants
#define N_IMG  32
#define CI_TOT 64
#define HH     128
#define WW     128
#define CO_TOT 128
#define HO     126
#define WO     126

#define TPX 16
#define TPY 8
#define NTILES 4096
#define GRID_MAIN 304     // 2 CTAs/SM x 152 SMs (GB300)

// ---- packed operand scratch (device globals; no allocation) ----
// g_xP2: bf16x2, [n(32)][chunk(4)][h(128)] rows of 256 swizzled 16B units
//        unit u (= w*2 + half) stored at u ^ ((u>>3)&1).  +1024 tail pad.
__device__ unsigned g_xP2[32u * 4u * 128u * 128u * 8u + 1024u];
// g_wP3: pre-swizzled smem byte image of ws: [chunk(4)][tap(9)][256 units x 16B]
__device__ uint4 g_wP3[4 * 9 * 256];

// merged pack kernel: blocks < 8192 pack x; blocks >= 8192 pack w
__global__ void pack_kernel(const float* __restrict__ x, const float* __restrict__ w) {
    if (blockIdx.x < 8192) {
        unsigned i = blockIdx.x * 256 + threadIdx.x;
        unsigned wq    = i & 127;
        unsigned h     = (i >> 7) & 127;
        unsigned chunk = (i >> 14) & 3;
        unsigned n     = i >> 16;
        const float* src = x + (((size_t)(n * 64 + chunk * 16)) * 128 + h) * 128 + wq;
        unsigned o[8];
#pragma unroll
        for (int c2 = 0; c2 < 8; c2++) {
            float v0 = src[(size_t)(2 * c2) * 16384];
            float v1 = src[(size_t)(2 * c2 + 1) * 16384];
            __nv_bfloat162 p = __float22bfloat162_rn(make_float2(v0, v1));
            o[c2] = *reinterpret_cast<unsigned*>(&p);
        }
        size_t rowb = (size_t)(((n * 4 + chunk) * 128 + h)) * 1024;
        unsigned u0 = wq * 2, u1 = wq * 2 + 1;
        unsigned s0 = u0 ^ ((u0 >> 3) & 1);
        unsigned s1 = u1 ^ ((u1 >> 3) & 1);
        *reinterpret_cast<uint4*>(&g_xP2[rowb + s0 * 4]) =
            make_uint4(o[0], o[1], o[2], o[3]);
        *reinterpret_cast<uint4*>(&g_xP2[rowb + s1 * 4]) =
            make_uint4(o[4], o[5], o[6], o[7]);
    } else {
        int i = (blockIdx.x - 8192) * 256 + threadIdx.x;   // 9216 units
        if (i >= 4 * 9 * 256) return;
        int u     = i & 255;
        int tap   = (i >> 8) % 9;
        int chunk = i / (9 * 256);
        int co = u >> 1;
        int h  = u & 1;
        unsigned o[4];
#pragma unroll
        for (int j = 0; j < 4; j++) {
            int ci = chunk * 16 + h * 8 + 2 * j;
            float w0 = w[((size_t)co * 64 + ci) * 9 + tap];
            float w1 = w[((size_t)co * 64 + ci + 1) * 9 + tap];
            __nv_bfloat162 p = __float22bfloat162_rn(make_float2(w0, w1));
            o[j] = *reinterpret_cast<unsigned*>(&p);
        }
        unsigned us = (unsigned)u ^ ((unsigned)(u >> 3) & 1);
        g_wP3[(chunk * 9 + tap) * 256 + us] = make_uint4(o[0], o[1], o[2], o[3]);
    }
}

// ---- smem layout (bytes), double buffered ----
#define SMEM_XS0 0
#define SMEM_XS1 6400
#define SMEM_WS0 12800
#define SMEM_WS1 49664
#define SMEM_BS  86528
#define SMEM_RED 87040
#define SMEM_MBAR 89088
#define SMEM_TOTAL 89216

#define XS_ROW_STRIDE 640

__device__ __forceinline__ void ldsm4(unsigned r[4], unsigned addr) {
    asm volatile("ldmatrix.sync.aligned.m8n8.x4.shared.b16 {%0,%1,%2,%3}, [%4];"
                 : "=r"(r[0]), "=r"(r[1]), "=r"(r[2]), "=r"(r[3]) : "r"(addr));
}
__device__ __forceinline__ void mbar_init(unsigned mbar, unsigned cnt) {
    asm volatile("mbarrier.init.shared.b64 [%0], %1;" :: "r"(mbar), "r"(cnt) : "memory");
}
__device__ __forceinline__ void mbar_expect_tx(unsigned mbar, unsigned tx) {
    asm volatile("mbarrier.arrive.expect_tx.shared.b64 _, [%0], %1;"
                 :: "r"(mbar), "r"(tx) : "memory");
}
__device__ __forceinline__ void bulk_g2s(unsigned dst, const void* src,
                                         unsigned sz, unsigned mbar) {
    asm volatile("cp.async.bulk.shared::cta.global.mbarrier::complete_tx::bytes "
                 "[%0], [%1], %2, [%3];"
                 :: "r"(dst), "l"(src), "r"(sz), "r"(mbar) : "memory");
}
__device__ __forceinline__ void mbar_wait(unsigned mbar, unsigned parity) {
    unsigned done;
    asm volatile(
        "{\n\t.reg .pred p;\n\t"
        "mbarrier.try_wait.parity.acquire.cta.shared::cta.b64 p, [%1], %2;\n\t"
        "selp.b32 %0, 1, 0, p;\n\t}"
        : "=r"(done) : "r"(mbar), "r"(parity) : "memory");
    while (!done) {
        asm volatile(
            "{\n\t.reg .pred p;\n\t"
            "mbarrier.try_wait.parity.acquire.cta.shared::cta.b64 p, [%1], %2, 0x989680;\n\t"
            "selp.b32 %0, 1, 0, p;\n\t}"
            : "=r"(done) : "r"(mbar), "r"(parity) : "memory");
    }
}
__device__ __forceinline__ void mma_bf16(float d[4], const unsigned a[4],
                                         unsigned b0, unsigned b1) {
    asm volatile(
        "mma.sync.aligned.m16n8k16.row.col.f32.bf16.bf16.f32 "
        "{%0,%1,%2,%3}, {%4,%5,%6,%7}, {%8,%9}, {%0,%1,%2,%3};\n"
        : "+f"(d[0]), "+f"(d[1]), "+f"(d[2]), "+f"(d[3])
        : "r"(a[0]), "r"(a[1]), "r"(a[2]), "r"(a[3]), "r"(b0), "r"(b1));
}

__global__ __launch_bounds__(256, 2)
void conv_mma_kernel(const float* __restrict__ bias, float* __restrict__ out) {
    extern __shared__ unsigned char sm[];
    const unsigned smb = (unsigned)__cvta_generic_to_shared(sm);

    const int tid  = threadIdx.x;
    const int wid  = tid >> 5;
    const int lane = tid & 31;
    const int q    = lane & 3;
    const int g    = lane >> 2;
    const int pg   = wid >> 2;      // pixel group: y rows 4pg..4pg+3
    const int cg   = wid & 3;       // co group: cg*32..+31
    const int nb   = cg * 32;
    const int bid  = blockIdx.x;

    float* bs  = (float*)(sm + SMEM_BS);
    float* red = (float*)(sm + SMEM_RED);   // [4 cg][8 rows][16 x]

    if (tid < CO_TOT) bs[tid] = bias[tid];
    if (tid == 0) {
        mbar_init(smb + SMEM_MBAR, 1);
        mbar_init(smb + SMEM_MBAR + 8, 1);
    }
    __syncthreads();

    // per-lane swizzled A offsets, one per kx shift
    unsigned axk[3];
#pragma unroll
    for (int kx = 0; kx < 3; kx++) {
        unsigned u = (unsigned)((kx + (lane & 15)) * 2 + (lane >> 4));
        axk[kx] = (u ^ ((u >> 3) & 1)) * 16;
    }
    // B offsets: 2 ldsm4 cover this warp's 32 co
    unsigned boff[2];
    {
        int co_off = (lane & 7) | ((lane >> 4) << 3);
        int h      = (lane >> 3) & 1;
#pragma unroll
        for (int t = 0; t < 2; t++) {
            unsigned u = (unsigned)((nb + 16 * t + co_off) * 2 + h);
            u ^= (u >> 3) & 1;
            boff[t] = u * 16;
        }
    }

    float d[4][4][4];
#pragma unroll
    for (int m = 0; m < 4; m++)
#pragma unroll
        for (int t = 0; t < 4; t++)
#pragma unroll
            for (int j = 0; j < 4; j++) d[m][t][j] = 0.0f;

    const int my_tiles = (NTILES - bid + GRID_MAIN - 1) / GRID_MAIN;
    const int total_it = my_tiles * 4;

    // prefetch for flat iteration index (tile = bid + (it>>2)*GRID, chunk = it&3)
    auto prefetch = [&](int it) {
        if (tid != 0 || it >= total_it) return;
        int tile  = bid + (it >> 2) * GRID_MAIN;
        int chunk = it & 3;
        int n   = tile >> 7;
        int rem = tile & 127;
        int py0 = (rem >> 3) * TPY;
        int px0 = (rem & 7) * TPX;
        int pbuf = it & 1;
        unsigned xb = smb + (pbuf ? SMEM_XS1 : SMEM_XS0);
        unsigned wb = smb + (pbuf ? SMEM_WS1 : SMEM_WS0);
        unsigned mbar = smb + SMEM_MBAR + pbuf * 8;
        mbar_expect_tx(mbar, 36864u + 10u * 576u);
        bulk_g2s(wb, &g_wP3[chunk * 9 * 256], 36864u, mbar);
#pragma unroll
        for (int r = 0; r < 10; r++) {
            int gy = py0 + r;
            int gyc = gy < 127 ? gy : 127;
            const unsigned* src =
                &g_xP2[((size_t)((n * 4 + chunk) * 128 + gyc)) * 1024 + (size_t)px0 * 8];
            bulk_g2s(xb + (unsigned)(r * XS_ROW_STRIDE), src, 576u, mbar);
        }
    };

    prefetch(0);

    for (int it = 0; it < total_it; it++) {
        mbar_wait(smb + SMEM_MBAR + (it & 1) * 8, (it >> 1) & 1);
        __syncthreads();
        prefetch(it + 1);

        unsigned xb = smb + ((it & 1) ? SMEM_XS1 : SMEM_XS0);
        unsigned wb = smb + ((it & 1) ? SMEM_WS1 : SMEM_WS0);
        const unsigned arow = (unsigned)(4 * pg) * XS_ROW_STRIDE;

        // kx-outer: 6 A row-fragments loaded once, reused across ky AND 4 m-tiles
#pragma unroll
        for (int kx = 0; kx < 3; kx++) {
            unsigned a[6][4];
#pragma unroll
            for (int rr = 0; rr < 6; rr++)
                ldsm4(a[rr], xb + arow + (unsigned)(rr * XS_ROW_STRIDE) + axk[kx]);
#pragma unroll
            for (int ky = 0; ky < 3; ky++) {
                const int tap = ky * 3 + kx;
#pragma unroll
                for (int t = 0; t < 2; t++) {
                    unsigned b[4];
                    ldsm4(b, wb + (unsigned)(tap * 4096) + boff[t]);
#pragma unroll
                    for (int m = 0; m < 4; m++) {
                        mma_bf16(d[m][2 * t],     a[m + ky], b[0], b[1]);
                        mma_bf16(d[m][2 * t + 1], a[m + ky], b[2], b[3]);
                    }
                }
            }
        }

        if ((it & 3) == 3) {
            // ---- per-tile epilogue: +bias, min over 32 co, combine, store ----
            int tile = bid + (it >> 2) * GRID_MAIN;
            int n   = tile >> 7;
            int rem = tile & 127;
            int y0  = (rem >> 3) * TPY;
            int x0  = (rem & 7) * TPX;

#pragma unroll
            for (int m = 0; m < 4; m++) {
                float mlo = INFINITY, mhi = INFINITY;
#pragma unroll
                for (int t = 0; t < 4; t++) {
                    float b0 = bs[nb + 8 * t + 2 * q];
                    float b1 = bs[nb + 8 * t + 2 * q + 1];
                    mlo = fminf(mlo, fminf(d[m][t][0] + b0, d[m][t][1] + b1));
                    mhi = fminf(mhi, fminf(d[m][t][2] + b0, d[m][t][3] + b1));
                    d[m][t][0] = 0.0f; d[m][t][1] = 0.0f;
                    d[m][t][2] = 0.0f; d[m][t][3] = 0.0f;
                }
                mlo = fminf(mlo, __shfl_xor_sync(0xFFFFFFFFu, mlo, 1));
                mlo = fminf(mlo, __shfl_xor_sync(0xFFFFFFFFu, mlo, 2));
                mhi = fminf(mhi, __shfl_xor_sync(0xFFFFFFFFu, mhi, 1));
                mhi = fminf(mhi, __shfl_xor_sync(0xFFFFFFFFu, mhi, 2));
                if (q == 0) {
                    red[(cg * 8 + pg * 4 + m) * 16 + g]     = mlo;
                    red[(cg * 8 + pg * 4 + m) * 16 + g + 8] = mhi;
                }
            }
            __syncthreads();

            if (tid < TPY * TPX) {
                int yl = tid >> 4, xl = tid & 15;
                int yy = y0 + yl, xx = x0 + xl;
                if (yy < HO && xx < WO) {
                    float v = fminf(
                        fminf(red[yl * 16 + xl], red[(8 + yl) * 16 + xl]),
                        fminf(red[(16 + yl) * 16 + xl], red[(24 + yl) * 16 + xl]));
                    out[((size_t)n * HO + yy) * WO + xx] = tanhf(tanhf(v));
                }
            }
        }
    }
}

extern "C" void kernel_launch(void* const* d_in, const int* in_sizes, int n_in,
                              void* d_out, int out_size) {
    const float* x    = (const float*)d_in[0];
    const float* w    = (const float*)d_in[1];
    const float* bias = (const float*)d_in[2];
    float* out        = (float*)d_out;

    pack_kernel<<<8192 + 36, 256>>>(x, w);

    cudaFuncSetAttribute(conv_mma_kernel,
                         cudaFuncAttributeMaxDynamicSharedMemorySize, SMEM_TOTAL);

    conv_mma_kernel<<<GRID_MAIN, 256, SMEM_TOTAL>>>(bias, out);
}

// round 16
// speedup vs baseline: 1.0815x; 1.0815x over previous
#include <cuda_runtime.h>
#include <cuda_bf16.h>
#include <math.h>

// Problem constants
#define N_IMG  32
#define CI_TOT 64
#define HH     128
#define WW     128
#define CO_TOT 128
#define HO     126
#define WO     126

#define TPX 16
#define TPY 8

// ---- packed operand scratch (device globals; no allocation) ----
// g_xP2: bf16x2, [n(32)][chunk(4)][h(128)] rows of 256 swizzled 16B units
//        unit u (= w*2 + half) stored at u ^ ((u>>3)&1).  +1024 tail pad.
__device__ unsigned g_xP2[32u * 4u * 128u * 128u * 8u + 1024u];
// g_wP3: pre-swizzled smem byte image of ws: [chunk(4)][tap(9)][256 units x 16B]
__device__ uint4 g_wP3[4 * 9 * 256];

// merged pack kernel: blocks < 8192 pack x; blocks >= 8192 pack w
__global__ void pack_kernel(const float* __restrict__ x, const float* __restrict__ w) {
    if (blockIdx.x < 8192) {
        unsigned i = blockIdx.x * 256 + threadIdx.x;
        unsigned wq    = i & 127;
        unsigned h     = (i >> 7) & 127;
        unsigned chunk = (i >> 14) & 3;
        unsigned n     = i >> 16;
        const float* src = x + (((size_t)(n * 64 + chunk * 16)) * 128 + h) * 128 + wq;
        unsigned o[8];
#pragma unroll
        for (int c2 = 0; c2 < 8; c2++) {
            float v0 = src[(size_t)(2 * c2) * 16384];
            float v1 = src[(size_t)(2 * c2 + 1) * 16384];
            __nv_bfloat162 p = __float22bfloat162_rn(make_float2(v0, v1));
            o[c2] = *reinterpret_cast<unsigned*>(&p);
        }
        size_t rowb = (size_t)(((n * 4 + chunk) * 128 + h)) * 1024;
        unsigned u0 = wq * 2, u1 = wq * 2 + 1;
        unsigned s0 = u0 ^ ((u0 >> 3) & 1);
        unsigned s1 = u1 ^ ((u1 >> 3) & 1);
        *reinterpret_cast<uint4*>(&g_xP2[rowb + s0 * 4]) =
            make_uint4(o[0], o[1], o[2], o[3]);
        *reinterpret_cast<uint4*>(&g_xP2[rowb + s1 * 4]) =
            make_uint4(o[4], o[5], o[6], o[7]);
    } else {
        int i = (blockIdx.x - 8192) * 256 + threadIdx.x;   // 9216 units
        if (i >= 4 * 9 * 256) return;
        int u     = i & 255;
        int tap   = (i >> 8) % 9;
        int chunk = i / (9 * 256);
        int co = u >> 1;
        int h  = u & 1;
        unsigned o[4];
#pragma unroll
        for (int j = 0; j < 4; j++) {
            int ci = chunk * 16 + h * 8 + 2 * j;
            float w0 = w[((size_t)co * 64 + ci) * 9 + tap];
            float w1 = w[((size_t)co * 64 + ci + 1) * 9 + tap];
            __nv_bfloat162 p = __float22bfloat162_rn(make_float2(w0, w1));
            o[j] = *reinterpret_cast<unsigned*>(&p);
        }
        unsigned us = (unsigned)u ^ ((unsigned)(u >> 3) & 1);
        g_wP3[(chunk * 9 + tap) * 256 + us] = make_uint4(o[0], o[1], o[2], o[3]);
    }
}

// ---- smem layout (bytes), double buffered ----
// mbar block: full0@+0, full1@+8, empty0@+16, empty1@+24
#define SMEM_XS0 0
#define SMEM_XS1 6400
#define SMEM_WS0 12800
#define SMEM_WS1 49664
#define SMEM_BS  86528
#define SMEM_RED 87040
#define SMEM_MBAR 89088
#define SMEM_TOTAL 89216

#define XS_ROW_STRIDE 640

__device__ __forceinline__ void ldsm4(unsigned r[4], unsigned addr) {
    asm volatile("ldmatrix.sync.aligned.m8n8.x4.shared.b16 {%0,%1,%2,%3}, [%4];"
                 : "=r"(r[0]), "=r"(r[1]), "=r"(r[2]), "=r"(r[3]) : "r"(addr));
}
__device__ __forceinline__ void mbar_init(unsigned mbar, unsigned cnt) {
    asm volatile("mbarrier.init.shared.b64 [%0], %1;" :: "r"(mbar), "r"(cnt) : "memory");
}
__device__ __forceinline__ void mbar_expect_tx(unsigned mbar, unsigned tx) {
    asm volatile("mbarrier.arrive.expect_tx.shared.b64 _, [%0], %1;"
                 :: "r"(mbar), "r"(tx) : "memory");
}
__device__ __forceinline__ void mbar_arrive(unsigned mbar) {
    asm volatile("mbarrier.arrive.shared.b64 _, [%0];" :: "r"(mbar) : "memory");
}
__device__ __forceinline__ void bulk_g2s(unsigned dst, const void* src,
                                         unsigned sz, unsigned mbar) {
    asm volatile("cp.async.bulk.shared::cta.global.mbarrier::complete_tx::bytes "
                 "[%0], [%1], %2, [%3];"
                 :: "r"(dst), "l"(src), "r"(sz), "r"(mbar) : "memory");
}
__device__ __forceinline__ void mbar_wait(unsigned mbar, unsigned parity) {
    unsigned done;
    asm volatile(
        "{\n\t.reg .pred p;\n\t"
        "mbarrier.try_wait.parity.acquire.cta.shared::cta.b64 p, [%1], %2;\n\t"
        "selp.b32 %0, 1, 0, p;\n\t}"
        : "=r"(done) : "r"(mbar), "r"(parity) : "memory");
    while (!done) {
        asm volatile(
            "{\n\t.reg .pred p;\n\t"
            "mbarrier.try_wait.parity.acquire.cta.shared::cta.b64 p, [%1], %2, 0x989680;\n\t"
            "selp.b32 %0, 1, 0, p;\n\t}"
            : "=r"(done) : "r"(mbar), "r"(parity) : "memory");
    }
}
__device__ __forceinline__ void mma_bf16(float d[4], const unsigned a[4],
                                         unsigned b0, unsigned b1) {
    asm volatile(
        "mma.sync.aligned.m16n8k16.row.col.f32.bf16.bf16.f32 "
        "{%0,%1,%2,%3}, {%4,%5,%6,%7}, {%8,%9}, {%0,%1,%2,%3};\n"
        : "+f"(d[0]), "+f"(d[1]), "+f"(d[2]), "+f"(d[3])
        : "r"(a[0]), "r"(a[1]), "r"(a[2]), "r"(a[3]), "r"(b0), "r"(b1));
}

__global__ __launch_bounds__(256, 2)
void conv_mma_kernel(const float* __restrict__ bias, float* __restrict__ out) {
    extern __shared__ unsigned char sm[];
    const unsigned smb = (unsigned)__cvta_generic_to_shared(sm);

    const int tid  = threadIdx.x;
    const int wid  = tid >> 5;
    const int lane = tid & 31;
    const int q    = lane & 3;
    const int g    = lane >> 2;
    const int pg   = wid >> 2;      // pixel group: y rows 4pg..4pg+3
    const int cg   = wid & 3;       // co group: cg*32..+31
    const int nb   = cg * 32;

    const int x0 = blockIdx.x * TPX;
    const int y0 = blockIdx.y * TPY;
    const int n  = blockIdx.z;

    // de-phase co-resident CTAs (neutral but free)
    const int cbase = 2 * ((blockIdx.x ^ blockIdx.y ^ blockIdx.z) & 1);

    float* bs  = (float*)(sm + SMEM_BS);
    float* red = (float*)(sm + SMEM_RED);   // [4 cg][8 rows][16 x]

    if (tid < CO_TOT) bs[tid] = bias[tid];
    if (tid == 0) {
        mbar_init(smb + SMEM_MBAR,      1);   // full0
        mbar_init(smb + SMEM_MBAR + 8,  1);   // full1
        mbar_init(smb + SMEM_MBAR + 16, 8);   // empty0 (8 warp arrivals)
        mbar_init(smb + SMEM_MBAR + 24, 8);   // empty1
    }
    __syncthreads();

    // per-lane swizzled A offsets, one per kx shift
    unsigned axk[3];
#pragma unroll
    for (int kx = 0; kx < 3; kx++) {
        unsigned u = (unsigned)((kx + (lane & 15)) * 2 + (lane >> 4));
        axk[kx] = (u ^ ((u >> 3) & 1)) * 16;
    }
    // B offsets: 2 ldsm4 cover this warp's 32 co
    unsigned boff[2];
    {
        int co_off = (lane & 7) | ((lane >> 4) << 3);
        int h      = (lane >> 3) & 1;
#pragma unroll
        for (int t = 0; t < 2; t++) {
            unsigned u = (unsigned)((nb + 16 * t + co_off) * 2 + h);
            u ^= (u >> 3) & 1;
            boff[t] = u * 16;
        }
    }

    float d[4][4][4];
#pragma unroll
    for (int m = 0; m < 4; m++)
#pragma unroll
        for (int t = 0; t < 4; t++)
#pragma unroll
            for (int j = 0; j < 4; j++) d[m][t][j] = 0.0f;

    // ---- prefetch iteration it (buffer it&1) from chunk (it+cbase)&3 ----
    auto prefetch = [&](int it) {
        int chunk = (it + cbase) & 3;
        int pbuf = it & 1;
        unsigned xb = smb + (pbuf ? SMEM_XS1 : SMEM_XS0);
        unsigned wb = smb + (pbuf ? SMEM_WS1 : SMEM_WS0);
        unsigned mbar = smb + SMEM_MBAR + pbuf * 8;
        mbar_expect_tx(mbar, 36864u + 10u * 576u);
        bulk_g2s(wb, &g_wP3[chunk * 9 * 256], 36864u, mbar);
#pragma unroll
        for (int r = 0; r < 10; r++) {
            int gy = y0 + r;
            int gyc = gy < 127 ? gy : 127;
            const unsigned* src =
                &g_xP2[((size_t)((n * 4 + chunk) * 128 + gyc)) * 1024 + (size_t)x0 * 8];
            bulk_g2s(xb + (unsigned)(r * XS_ROW_STRIDE), src, 576u, mbar);
        }
    };

    if (tid == 0) prefetch(0);

    for (int it = 0; it < 4; it++) {
        // warp 0: issue next prefetch (guarded by empty barrier for buffer reuse)
        if (tid == 0 && it < 3) {
            int j = it + 1;
            if (j >= 2) mbar_wait(smb + SMEM_MBAR + 16 + (j & 1) * 8, 0);
            prefetch(j);
        }
        // all warps: wait data-ready for this buffer (no CTA-wide barrier)
        mbar_wait(smb + SMEM_MBAR + (it & 1) * 8, (it >> 1) & 1);

        unsigned xb = smb + ((it & 1) ? SMEM_XS1 : SMEM_XS0);
        unsigned wb = smb + ((it & 1) ? SMEM_WS1 : SMEM_WS0);
        const unsigned arow = (unsigned)(4 * pg) * XS_ROW_STRIDE;

        // kx-outer: 6 A row-fragments loaded once, reused across ky AND 4 m-tiles
#pragma unroll
        for (int kx = 0; kx < 3; kx++) {
            unsigned a[6][4];
#pragma unroll
            for (int rr = 0; rr < 6; rr++)
                ldsm4(a[rr], xb + arow + (unsigned)(rr * XS_ROW_STRIDE) + axk[kx]);
#pragma unroll
            for (int ky = 0; ky < 3; ky++) {
                const int tap = ky * 3 + kx;
#pragma unroll
                for (int t = 0; t < 2; t++) {
                    unsigned b[4];
                    ldsm4(b, wb + (unsigned)(tap * 4096) + boff[t]);
#pragma unroll
                    for (int m = 0; m < 4; m++) {
                        mma_bf16(d[m][2 * t],     a[m + ky], b[0], b[1]);
                        mma_bf16(d[m][2 * t + 1], a[m + ky], b[2], b[3]);
                    }
                }
            }
        }

        // this warp is done reading buffer it&1
        if (lane == 0) mbar_arrive(smb + SMEM_MBAR + 16 + (it & 1) * 8);
    }

    // ---- epilogue: +bias, min over this warp's 32 co ----
#pragma unroll
    for (int m = 0; m < 4; m++) {
        float mlo = INFINITY, mhi = INFINITY;
#pragma unroll
        for (int t = 0; t < 4; t++) {
            float b0 = bs[nb + 8 * t + 2 * q];
            float b1 = bs[nb + 8 * t + 2 * q + 1];
            mlo = fminf(mlo, fminf(d[m][t][0] + b0, d[m][t][1] + b1));
            mhi = fminf(mhi, fminf(d[m][t][2] + b0, d[m][t][3] + b1));
        }
        mlo = fminf(mlo, __shfl_xor_sync(0xFFFFFFFFu, mlo, 1));
        mlo = fminf(mlo, __shfl_xor_sync(0xFFFFFFFFu, mlo, 2));
        mhi = fminf(mhi, __shfl_xor_sync(0xFFFFFFFFu, mhi, 1));
        mhi = fminf(mhi, __shfl_xor_sync(0xFFFFFFFFu, mhi, 2));
        if (q == 0) {
            red[(cg * 8 + pg * 4 + m) * 16 + g]     = mlo;
            red[(cg * 8 + pg * 4 + m) * 16 + g + 8] = mhi;
        }
    }
    __syncthreads();

    // ---- combine 4 co-groups, tanh(tanh), store ----
    if (tid < TPY * TPX) {
        int yl = tid >> 4, xl = tid & 15;
        int yy = y0 + yl, xx = x0 + xl;
        if (yy < HO && xx < WO) {
            float v = fminf(fminf(red[yl * 16 + xl], red[(8 + yl) * 16 + xl]),
                            fminf(red[(16 + yl) * 16 + xl], red[(24 + yl) * 16 + xl]));
            out[((size_t)n * HO + yy) * WO + xx] = tanhf(tanhf(v));
        }
    }
}

extern "C" void kernel_launch(void* const* d_in, const int* in_sizes, int n_in,
                              void* d_out, int out_size) {
    const float* x    = (const float*)d_in[0];
    const float* w    = (const float*)d_in[1];
    const float* bias = (const float*)d_in[2];
    float* out        = (float*)d_out;

    pack_kernel<<<8192 + 36, 256>>>(x, w);

    cudaFuncSetAttribute(conv_mma_kernel,
                         cudaFuncAttributeMaxDynamicSharedMemorySize, SMEM_TOTAL);

    dim3 grid((WO + TPX - 1) / TPX,   // 8
              (HO + TPY - 1) / TPY,   // 16
              N_IMG);                 // 32
    conv_mma_kernel<<<grid, 256, SMEM_TOTAL>>>(bias, out);
}